// round 17
// baseline (speedup 1.0000x reference)
#include <cuda_runtime.h>
#include <cstdint>

// Fixed shapes
#define TT    16
#define HH    1280
#define WW    1280
#define NB    64
#define W4    (WW / 4)            // 320 float4 per row
#define HW4   (HH * W4)           // 409,600 float4 per frame
#define SNTHR W4                  // scan kernel: 320 thr, one block per row
#define SWARP (SNTHR / 32)
#define RNTHR 256                 // reduce kernel threads
#define RNBLK (HW4 / RNTHR)       // 1600 blocks
#define NSLOT 32

__device__ __align__(16) float g_wmap[HH * WW];  // per-pixel box-coverage weight
__device__ double       g_slots[NSLOT];          // zeroed at load; reset each replay
__device__ unsigned int g_count = 0u;

// ---------------------------------------------------------------------------
// Kernel 1: build the float weight map. One block per row; diff-array +
// block prefix scan (the R3-proven machinery), then one STG.128 per thread.
// ---------------------------------------------------------------------------
__global__ void __launch_bounds__(SNTHR) wmap_kernel(const int* __restrict__ boxes) {
    __shared__ int sdiff[WW];
    __shared__ int wsum[SWARP];

    const int tid  = threadIdx.x;        // 0..319
    const int y    = blockIdx.x;
    const int lane = tid & 31;
    const int wid  = tid >> 5;

    reinterpret_cast<int4*>(sdiff)[tid] = make_int4(0, 0, 0, 0);
    __syncthreads();

    if (tid < NB) {
        int4 b = __ldg(reinterpret_cast<const int4*>(boxes) + tid);  // x1,y1,x2,y2
        if (b.y <= y && y < b.w) {
            atomicAdd(&sdiff[b.x],  1);
            atomicAdd(&sdiff[b.z], -1);      // x2 <= 1279 < WW
        }
    }
    __syncthreads();

    int4 c = reinterpret_cast<const int4*>(sdiff)[tid];
    int s0 = c.x, s1 = s0 + c.y, s2 = s1 + c.z, s3 = s2 + c.w;
    const int tot = s3;

    int v = tot;
#pragma unroll
    for (int off = 1; off < 32; off <<= 1) {
        int n = __shfl_up_sync(0xFFFFFFFFu, v, off);
        if (lane >= off) v += n;
    }
    if (lane == 31) wsum[wid] = v;
    __syncthreads();

    int wprefix = 0;
#pragma unroll
    for (int i = 0; i < SWARP; i++)
        if (i < wid) wprefix += wsum[i];
    const int base = wprefix + (v - tot);

    float4 w = make_float4((float)(base + s0), (float)(base + s1),
                           (float)(base + s2), (float)(base + s3));
    reinterpret_cast<float4*>(g_wmap)[y * W4 + tid] = w;
}

// ---------------------------------------------------------------------------
// Kernel 2: barrier-free streaming dot. 256 thr, 8 blocks/SM (64 warps = max).
// gid linear over the plane: 1 weight float4 + 16 frame float4 (prefetch 4,
// then 3 batches of 4). Warp+block reduce, slot atomic, last block writes out.
// ---------------------------------------------------------------------------
__global__ void __launch_bounds__(RNTHR, 8) reduce_kernel(const float* __restrict__ data,
                                                          float* __restrict__ out) {
    const int tid = threadIdx.x;
    const int gid = blockIdx.x * RNTHR + tid;    // 0..HW4-1

    const float4* p = reinterpret_cast<const float4*>(data) + gid;
    float4 v0 = __ldg(p + 0 * (size_t)HW4);
    float4 v1 = __ldg(p + 1 * (size_t)HW4);
    float4 v2 = __ldg(p + 2 * (size_t)HW4);
    float4 v3 = __ldg(p + 3 * (size_t)HW4);
    const float4 w = reinterpret_cast<const float4*>(g_wmap)[gid];

    float a0 = (v0.x + v1.x) + (v2.x + v3.x);
    float a1 = (v0.y + v1.y) + (v2.y + v3.y);
    float a2 = (v0.z + v1.z) + (v2.z + v3.z);
    float a3 = (v0.w + v1.w) + (v2.w + v3.w);

#pragma unroll
    for (int t = 4; t < TT; t += 4) {
        float4 q0 = __ldg(p + (size_t)(t + 0) * HW4);
        float4 q1 = __ldg(p + (size_t)(t + 1) * HW4);
        float4 q2 = __ldg(p + (size_t)(t + 2) * HW4);
        float4 q3 = __ldg(p + (size_t)(t + 3) * HW4);
        a0 += (q0.x + q1.x) + (q2.x + q3.x);
        a1 += (q0.y + q1.y) + (q2.y + q3.y);
        a2 += (q0.z + q1.z) + (q2.z + q3.z);
        a3 += (q0.w + q1.w) + (q2.w + q3.w);
    }

    float s = fmaf(w.x, a0, fmaf(w.y, a1, fmaf(w.z, a2, w.w * a3)));

#pragma unroll
    for (int off = 16; off > 0; off >>= 1)
        s += __shfl_down_sync(0xFFFFFFFFu, s, off);

    __shared__ float warp_sums[RNTHR / 32];
    const int lane = tid & 31;
    const int wid  = tid >> 5;
    if (lane == 0) warp_sums[wid] = s;
    __syncthreads();

    if (tid == 0) {
        float bsum = warp_sums[0];
#pragma unroll
        for (int i = 1; i < RNTHR / 32; i++) bsum += warp_sums[i];

        atomicAdd(&g_slots[blockIdx.x & (NSLOT - 1)], (double)bsum);
        __threadfence();
        unsigned old = atomicAdd(&g_count, 1u);
        if (old == RNBLK - 1u) {
            __threadfence();
            double total = 0.0;
            volatile double* vs = g_slots;
#pragma unroll
            for (int i = 0; i < NSLOT; i++) {
                total += vs[i];
                vs[i] = 0.0;                 // reset for next graph replay
            }
            out[0] = (float)total;
            __threadfence();
            g_count = 0u;
        }
    }
}

extern "C" void kernel_launch(void* const* d_in, const int* in_sizes, int n_in,
                              void* d_out, int out_size) {
    const float* data  = (const float*)d_in[0];  // (16,1280,1280) fp32
    const int*   boxes = (const int*)d_in[1];    // (64,4) int32 [x1,y1,x2,y2]
    float*       out   = (float*)d_out;

    wmap_kernel<<<HH, SNTHR>>>(boxes);
    reduce_kernel<<<RNBLK, RNTHR>>>(data, out);
}